// round 10
// baseline (speedup 1.0000x reference)
#include <cuda_runtime.h>

#define KS     5
#define TAPS   25
#define NKP    13          // live k-pairs (k=25: pair 12 lane1 zero-padded)
#define NKPAD  14          // padded row length so each (c,m) row is 16B-aligned (112B)
#define CCH    3
#define HALO   2
#define TILE_W 32
#define TILE_H 16
#define RPT    2           // pixels (rows) per thread
#define SM_W   (TILE_W + 2*HALO)   // 36
#define SM_H   (TILE_H + 2*HALO)   // 20
#define NTHREADS 256

typedef unsigned long long u64;

__device__ __forceinline__ u64 pack2(float lo, float hi) {
    u64 r;
    asm("mov.b64 %0, {%1, %2};" : "=l"(r) : "f"(lo), "f"(hi));
    return r;
}
__device__ __forceinline__ void unpack2(u64 v, float& lo, float& hi) {
    asm("mov.b64 {%0, %1}, %2;" : "=f"(lo), "=f"(hi) : "l"(v));
}
__device__ __forceinline__ void ffma2(u64& d, u64 a, u64 b) {
    asm("fma.rn.f32x2 %0, %1, %2, %0;" : "+l"(d) : "l"(a), "l"(b));
}
__device__ __forceinline__ const float& st_at(const float* st, int c, int r, int col) {
    return st[(c * SM_H + r) * SM_W + col];
}

__global__ void __launch_bounds__(NTHREADS, 2)
ho_kpair3_kernel(const float* __restrict__ x,
                 const float* __restrict__ cw,   // [25][3][5][5]
                 const float* __restrict__ cb,   // [25]
                 float* __restrict__ out,
                 int H, int W)
{
    __shared__ float s_tile[CCH * SM_H * SM_W];            // 2160 f = 8.6 KB
    __shared__ __align__(16) u64 s_w2[CCH * TAPS * NKPAD]; // [(c*25+m)*14+kp] = 8.4 KB
    __shared__ u64 s_b2[NKP];

    const int tid = threadIdx.x;

    // Stage weights as k-pairs; kp=13 is zero padding (alignment only).
    for (int idx = tid; idx < CCH * TAPS * NKPAD; idx += NTHREADS) {
        int c   = idx / (TAPS * NKPAD);
        int rem = idx % (TAPS * NKPAD);
        int m   = rem / NKPAD;
        int kp  = rem % NKPAD;
        int k0 = 2 * kp, k1 = k0 + 1;
        float w0 = (k0 < TAPS) ? cw[(k0 * CCH + c) * TAPS + m] : 0.0f;
        float w1 = (k1 < TAPS) ? cw[(k1 * CCH + c) * TAPS + m] : 0.0f;
        s_w2[idx] = pack2(w0, w1);
    }
    if (tid < NKP) {
        int k0 = 2 * tid, k1 = k0 + 1;
        s_b2[tid] = pack2(cb[k0], (k1 < TAPS) ? cb[k1] : 0.0f);
    }

    const int b  = blockIdx.z;
    const int h0 = blockIdx.y * TILE_H;
    const int w0 = blockIdx.x * TILE_W;
    const float* xb = x + (size_t)b * CCH * H * W;

    // Stage input tile + halo (zero-padded at borders)
    for (int i = tid; i < CCH * SM_H * SM_W; i += NTHREADS) {
        int c   = i / (SM_H * SM_W);
        int r   = (i / SM_W) % SM_H;
        int col = i % SM_W;
        int hh = h0 + r   - HALO;
        int ww = w0 + col - HALO;
        float v = 0.0f;
        if (hh >= 0 && hh < H && ww >= 0 && ww < W)
            v = xb[(size_t)c * H * W + (size_t)hh * W + ww];
        s_tile[(c * SM_H + r) * SM_W + col] = v;
    }
    __syncthreads();

    const int tx = tid & 31;          // 0..31
    const int ty = tid >> 5;          // 0..7
    const int ry = ty * RPT;

    // ---- Pass 1: dynamic weights packed along k:
    //      wacc[p][kp] = (w_{2kp}(pixel p), w_{2kp+1}(pixel p))
    u64 wacc[RPT][NKP];
#pragma unroll
    for (int p = 0; p < RPT; p++)
#pragma unroll
        for (int q = 0; q < NKP; q++)
            wacc[p][q] = s_b2[q];

#pragma unroll
    for (int c = 0; c < CCH; c++) {
#pragma unroll
        for (int m = 0; m < TAPS; m++) {
            const int i = m / KS, j = m % KS;
            u64 nd[RPT];
#pragma unroll
            for (int p = 0; p < RPT; p++) {
                float v = st_at(s_tile, c, ry + p + i, tx + j);
                nd[p] = pack2(v, v);
            }
            const u64* wp = &s_w2[(c * TAPS + m) * NKPAD];
            // 6 x LDS.128 (two k-pairs each) + 1 x LDS.64 (pair 12)
#pragma unroll
            for (int q2 = 0; q2 < 6; q2++) {
                ulonglong2 wv = *reinterpret_cast<const ulonglong2*>(wp + 2 * q2);
#pragma unroll
                for (int p = 0; p < RPT; p++) {
                    ffma2(wacc[p][2 * q2    ], wv.x, nd[p]);
                    ffma2(wacc[p][2 * q2 + 1], wv.y, nd[p]);
                }
            }
            {
                u64 wv12 = wp[12];
#pragma unroll
                for (int p = 0; p < RPT; p++)
                    ffma2(wacc[p][12], wv12, nd[p]);
            }
        }
    }

    // ---- Pass 2: fold k-pairs into packed output (lane-split sums), horizontal-add
    float* ob = out + (size_t)b * CCH * H * W;
    const int h = h0 + ry;
    const int w = w0 + tx;

#pragma unroll
    for (int c = 0; c < CCH; c++) {
        u64 acc[RPT];
#pragma unroll
        for (int p = 0; p < RPT; p++)
            acc[p] = pack2(st_at(s_tile, c, ry + p + HALO, tx + HALO), 0.0f);  // residual lane0

#pragma unroll
        for (int q = 0; q < NKP; q++) {
            const int k0 = 2 * q, k1 = k0 + 1;
            const int i0 = k0 / KS, j0 = k0 % KS;
            const int i1 = (k1 < TAPS) ? k1 / KS : 0;
            const int j1 = (k1 < TAPS) ? k1 % KS : 0;
#pragma unroll
            for (int p = 0; p < RPT; p++) {
                float n0 = st_at(s_tile, c, ry + p + i0, tx + j0);
                float n1 = (k1 < TAPS) ? st_at(s_tile, c, ry + p + i1, tx + j1) : 0.0f;
                ffma2(acc[p], wacc[p][q], pack2(n0, n1));
            }
        }

        float* op = ob + (size_t)c * H * W + (size_t)h * W + w;
#pragma unroll
        for (int p = 0; p < RPT; p++) {
            float lo, hi;
            unpack2(acc[p], lo, hi);
            op[(size_t)p * W] = lo + hi;
        }
    }
}

extern "C" void kernel_launch(void* const* d_in, const int* in_sizes, int n_in,
                              void* d_out, int out_size)
{
    const float* x  = (const float*)d_in[0];
    const float* cw = (const float*)d_in[1];
    const float* cb = (const float*)d_in[2];
    float* out      = (float*)d_out;

    const int H = 256, W = 256;
    const int B = in_sizes[0] / (CCH * H * W);   // 16

    dim3 grid(W / TILE_W, H / TILE_H, B);        // (8, 16, 16) = 2048 blocks
    ho_kpair3_kernel<<<grid, NTHREADS>>>(x, cw, cb, out, H, W);
}